// round 9
// baseline (speedup 1.0000x reference)
#include <cuda_runtime.h>
#include <cstdint>

#define TOK   2048
#define DIMSZ 1024
#define HID   2048
#define NE    8
#define NSLOT (2 * TOK)
#define QMAX  16256   // 127*128

typedef signed char s8;

// Scratch (allocation-free: __device__ globals)
__device__ float g_w[NSLOT];
__device__ int   g_cnt[NE];
__device__ int   g_list[NE * TOK];
__device__ __align__(128) s8 g_xqh[TOK * DIMSZ];
__device__ __align__(128) s8 g_xql[TOK * DIMSZ];
__device__ float g_sx[TOK];
__device__ __align__(128) s8 g_wfcqh[NE * HID * DIMSZ];
__device__ __align__(128) s8 g_wfcql[NE * HID * DIMSZ];
__device__ float g_swfc[NE * HID];
__device__ __align__(128) s8 g_wpqh[NE * DIMSZ * HID];
__device__ __align__(128) s8 g_wpql[NE * DIMSZ * HID];
__device__ float g_swp[NE * DIMSZ];
__device__ float g_h2[(size_t)NSLOT * HID];
__device__ __align__(128) s8 g_h2qh[NSLOT * HID];
__device__ __align__(128) s8 g_h2ql[NSLOT * HID];
__device__ float g_sh2[NSLOT];
__device__ float g_y[(size_t)NSLOT * DIMSZ];

// ---------------------------------------------------------------------------
// Helpers
// ---------------------------------------------------------------------------
__device__ __forceinline__ uint32_t smem_u32(const void* p) {
    uint32_t a;
    asm("{ .reg .u64 t; cvta.to.shared.u64 t, %1; cvt.u32.u64 %0, t; }" : "=r"(a) : "l"(p));
    return a;
}
__device__ __forceinline__ void ldm4(uint32_t* r, uint32_t addr) {
    asm volatile("ldmatrix.sync.aligned.m8n8.x4.shared.b16 {%0,%1,%2,%3}, [%4];"
        : "=r"(r[0]), "=r"(r[1]), "=r"(r[2]), "=r"(r[3]) : "r"(addr));
}
__device__ __forceinline__ void imma(int* c, const uint32_t* a, const uint32_t* b) {
    asm volatile(
        "mma.sync.aligned.m16n8k32.row.col.s32.s8.s8.s32 "
        "{%0,%1,%2,%3}, {%4,%5,%6,%7}, {%8,%9}, {%0,%1,%2,%3};"
        : "+r"(c[0]), "+r"(c[1]), "+r"(c[2]), "+r"(c[3])
        : "r"(a[0]), "r"(a[1]), "r"(a[2]), "r"(a[3]), "r"(b[0]), "r"(b[1]));
}
__device__ __forceinline__ void cp16(uint32_t dst, const void* src) {
    asm volatile("cp.async.cg.shared.global [%0], [%1], 16;" :: "r"(dst), "l"(src) : "memory");
}
__device__ __forceinline__ void cp_commit() {
    asm volatile("cp.async.commit_group;" ::: "memory");
}
template<int N> __device__ __forceinline__ void cp_wait() {
    asm volatile("cp.async.wait_group %0;" :: "n"(N) : "memory");
}
// (row, 16B-chunk c in 0..3) -> swizzled byte offset within one Nx64B mat
__device__ __forceinline__ uint32_t swzoff(uint32_t row, uint32_t c) {
    uint32_t q = (((row & 1u) << 2) | c) ^ ((row >> 1) & 7u);
    return ((row >> 1) << 7) + (q << 4);
}

// ---------------------------------------------------------------------------
__global__ void k_zero_counts() {
    if (threadIdx.x < NE) g_cnt[threadIdx.x] = 0;
}

// Per-row 14-bit quantize + split into int8 hi/lo.  R floats per row, 256 thr.
template<int R>
__global__ void k_quant(const float* __restrict__ src, s8* __restrict__ qh,
                        s8* __restrict__ ql, float* __restrict__ sc) {
    constexpr int J = R / 1024;   // float4s per thread
    __shared__ float red[8];
    int row = blockIdx.x, tid = threadIdx.x;
    const float4* s = (const float4*)(src + (size_t)row * R);
    float4 v[J];
    float m = 0.f;
#pragma unroll
    for (int j = 0; j < J; ++j) {
        v[j] = s[tid + j * 256];
        m = fmaxf(m, fmaxf(fmaxf(fabsf(v[j].x), fabsf(v[j].y)),
                           fmaxf(fabsf(v[j].z), fabsf(v[j].w))));
    }
#pragma unroll
    for (int o = 16; o > 0; o >>= 1) m = fmaxf(m, __shfl_xor_sync(~0u, m, o));
    if ((tid & 31) == 0) red[tid >> 5] = m;
    __syncthreads();
    float S = 1e-30f;
#pragma unroll
    for (int i = 0; i < 8; ++i) S = fmaxf(S, red[i]);
    float scale = (float)QMAX / S;

    char4* oh = (char4*)(qh + (size_t)row * R);
    char4* ol = (char4*)(ql + (size_t)row * R);
#pragma unroll
    for (int j = 0; j < J; ++j) {
        float e[4] = {v[j].x, v[j].y, v[j].z, v[j].w};
        int ah[4], al[4];
#pragma unroll
        for (int i = 0; i < 4; ++i) {
            int q = __float2int_rn(e[i] * scale);
            q = max(min(q, QMAX), -QMAX);
            ah[i] = (q + 64) >> 7;
            al[i] = q - (ah[i] << 7);
        }
        oh[tid + j * 256] = make_char4((s8)ah[0], (s8)ah[1], (s8)ah[2], (s8)ah[3]);
        ol[tid + j * 256] = make_char4((s8)al[0], (s8)al[1], (s8)al[2], (s8)al[3]);
    }
    if (tid == 0) sc[row] = S * (1.f / (float)QMAX);
}

// Router: one warp per token. logits -> softmax -> top2 -> renormalize (+1e-8)
__global__ void k_router(const float* __restrict__ x, const float* __restrict__ Wr) {
    int warp = threadIdx.x >> 5;
    int lane = threadIdx.x & 31;
    int t = blockIdx.x * 8 + warp;

    float acc[NE];
#pragma unroll
    for (int e = 0; e < NE; ++e) acc[e] = 0.f;

    const float* xr = x + (size_t)t * DIMSZ;
    for (int i = lane; i < DIMSZ; i += 32) {
        float xv = xr[i];
#pragma unroll
        for (int e = 0; e < NE; ++e) acc[e] = fmaf(xv, Wr[e * DIMSZ + i], acc[e]);
    }
#pragma unroll
    for (int e = 0; e < NE; ++e) {
#pragma unroll
        for (int o = 16; o > 0; o >>= 1)
            acc[e] += __shfl_xor_sync(0xffffffffu, acc[e], o);
    }
    if (lane == 0) {
        float m = acc[0];
#pragma unroll
        for (int e = 1; e < NE; ++e) m = fmaxf(m, acc[e]);
        float p[NE]; float Z = 0.f;
#pragma unroll
        for (int e = 0; e < NE; ++e) { p[e] = expf(acc[e] - m); Z += p[e]; }
        float invZ = 1.f / Z;
#pragma unroll
        for (int e = 0; e < NE; ++e) p[e] *= invZ;

        int e0 = 0;
#pragma unroll
        for (int e = 1; e < NE; ++e) if (p[e] > p[e0]) e0 = e;
        int e1 = (e0 == 0) ? 1 : 0;
#pragma unroll
        for (int e = 0; e < NE; ++e) { if (e != e0 && p[e] > p[e1]) e1 = e; }

        float s = p[e0] + p[e1] + 1e-8f;
        g_w[2 * t]     = p[e0] / s;
        g_w[2 * t + 1] = p[e1] / s;
        int q0 = atomicAdd(&g_cnt[e0], 1); g_list[e0 * TOK + q0] = 2 * t;
        int q1 = atomicAdd(&g_cnt[e1], 1); g_list[e1 * TOK + q1] = 2 * t + 1;
    }
}

// ---------------------------------------------------------------------------
// Grouped int8 GEMM: mma.sync m16n8k32 s8, 3-pass exact fixed-point:
//   dot = sA*sB*(16384*P1 + 128*(P2+P3))   [al*bl dropped, ~8e-5 rel]
// CTA = 128 threads (4 warps 2x2), tile 128x64 (MxN), warp tile 64x32.
// K-slab = 64 int8 (64B rows). 3-stage cp.async pipeline, 1 sync/slab.
// Stage layout: [Ah 8K][Al 8K][Bh 4K][Bl 4K] = 24 KB, XOR-swizzled 64B rows.
#define AMAT     8192
#define BMAT     4096
#define BH_OFF   (2 * AMAT)           // 16384
#define BL_OFF   (BH_OFF + BMAT)      // 20480
#define STG      24576
#define SLOT_OFF (3 * STG)            // 73728
#define AOFF_OFF (SLOT_OFF + 512)
#define ASC_OFF  (AOFF_OFF + 512)
#define GSMEM    (ASC_OFF + 512)

template<int KDIM, int NDIM, bool RELU2, int SHIFT, int PHASE>
__global__ void __launch_bounds__(128, 2)
k_gemm_i8() {
    constexpr int NSLAB = KDIM / 64;
    const s8* Aq  = (PHASE == 1) ? g_xqh : g_h2qh;
    const s8* Aql = (PHASE == 1) ? g_xql : g_h2ql;
    const float* sAarr = (PHASE == 1) ? g_sx : g_sh2;
    const s8* BqA  = (PHASE == 1) ? g_wfcqh : g_wpqh;
    const s8* BqlA = (PHASE == 1) ? g_wfcql : g_wpql;
    const float* sBA = (PHASE == 1) ? g_swfc : g_swp;

    int e   = blockIdx.z;
    int cnt = g_cnt[e];
    int m0  = blockIdx.y * 128;
    if (m0 >= cnt) return;
    int n0  = blockIdx.x * 64;
    const s8* Bh = BqA  + (size_t)e * NDIM * KDIM;
    const s8* Bl = BqlA + (size_t)e * NDIM * KDIM;
    const float* sB = sBA + e * NDIM;

    extern __shared__ char smem[];
    uint32_t sb = smem_u32(smem);
    int*   s_slot = (int*)(smem + SLOT_OFF);
    int*   s_aoff = (int*)(smem + AOFF_OFF);
    float* s_asc  = (float*)(smem + ASC_OFF);
    int tid = threadIdx.x, w = tid >> 5, lane = tid & 31;

    {
        int idx = m0 + tid;
        int sl  = g_list[e * TOK + ((idx < cnt) ? idx : m0)];
        s_slot[tid] = (idx < cnt) ? sl : -1;
        int ar = sl >> SHIFT;
        s_aoff[tid] = ar * KDIM;
        s_asc[tid]  = sAarr[ar];
    }
    __syncthreads();

    int lrow = lane & 7, lchunk = lane >> 3;
    int raoff[4];
    size_t boff[2];
#pragma unroll
    for (int j = 0; j < 4; ++j)
        raoff[j] = s_aoff[(4 * j + w) * 8 + lrow] + lchunk * 16;
#pragma unroll
    for (int j = 0; j < 2; ++j) {
        int row = (4 * j + w) * 8 + lrow;   // rows 0..63 over j,w
        boff[j] = (size_t)(n0 + row) * KDIM + lchunk * 16;
    }

    // issue one K-slab (64 int8/row): A 8 cp16 + B 4 cp16 per thread
    auto issue = [&](int ks, int stage) {
        int k0 = ks * 64;
        uint32_t stg = sb + (uint32_t)stage * STG;
#pragma unroll
        for (int j = 0; j < 4; ++j) {
            uint32_t row = (uint32_t)(4 * j + w) * 8 + lrow;
            uint32_t so = stg + swzoff(row, lchunk);
            cp16(so,        Aq  + raoff[j] + k0);
            cp16(so + AMAT, Aql + raoff[j] + k0);
        }
#pragma unroll
        for (int j = 0; j < 2; ++j) {
            uint32_t row = (uint32_t)(4 * j + w) * 8 + lrow;
            uint32_t so = stg + swzoff(row, lchunk);
            cp16(so + BH_OFF, Bh + boff[j] + k0);
            cp16(so + BL_OFF, Bl + boff[j] + k0);
        }
        cp_commit();
    };

    int wy = w >> 1, wx = w & 1;
    // ldmatrix per-lane bases (kk=0); kk=1 via ^0x20
    uint32_t aQ = (((lane & 1u) << 2) | (uint32_t)(lane >> 4)) ^ (((uint32_t)(lane & 15) >> 1) & 7u);
    uint32_t aB0 = sb + (uint32_t)((wy * 64 + (lane & 15)) >> 1) * 128 + aQ * 16;
    uint32_t brow = (uint32_t)(wx * 32 + ((lane >> 4) & 1) * 8 + (lane & 7));
    uint32_t bc   = (uint32_t)((lane >> 3) & 1);
    uint32_t bQ   = (((brow & 1u) << 2) | bc) ^ ((brow >> 1) & 7u);
    uint32_t bB0  = sb + BH_OFF + (brow >> 1) * 128 + bQ * 16;

    int acc1[4][4][4], acc23[4][4][4];
#pragma unroll
    for (int i = 0; i < 4; ++i)
#pragma unroll
        for (int j = 0; j < 4; ++j)
#pragma unroll
            for (int r = 0; r < 4; ++r) { acc1[i][j][r] = 0; acc23[i][j][r] = 0; }

    issue(0, 0);
    issue(1, 1);
    cp_wait<1>();
    __syncthreads();

#pragma unroll 1
    for (int ks = 0; ks < NSLAB; ++ks) {
        int cur = ks % 3;
        if (ks + 2 < NSLAB) issue(ks + 2, (ks + 2) % 3);
        else                cp_commit();

        uint32_t aS = aB0 + (uint32_t)cur * STG;
        uint32_t bS = bB0 + (uint32_t)cur * STG;
#pragma unroll
        for (int kk = 0; kk < 2; ++kk) {
            uint32_t ah[4][4], al[4][4], bh[2][4], bl[2][4];
#pragma unroll
            for (int mt = 0; mt < 4; ++mt) {
                uint32_t ad = (aS + mt * 1024) ^ (kk * 0x20);
                ldm4(ah[mt], ad);
                ldm4(al[mt], ad + AMAT);
            }
#pragma unroll
            for (int p = 0; p < 2; ++p) {
                uint32_t bd = (bS + p * 1024) ^ (kk * 0x20);
                ldm4(bh[p], bd);
                ldm4(bl[p], bd + BMAT);
            }
#pragma unroll
            for (int mt = 0; mt < 4; ++mt)
#pragma unroll
                for (int nt = 0; nt < 4; ++nt) {
                    const uint32_t* pbh = &bh[nt >> 1][(nt & 1) * 2];
                    const uint32_t* pbl = &bl[nt >> 1][(nt & 1) * 2];
                    imma(acc1[mt][nt], ah[mt], pbh);
                    imma(acc23[mt][nt], ah[mt], pbl);
                    imma(acc23[mt][nt], al[mt], pbh);
                }
        }
        cp_wait<1>();
        __syncthreads();
    }

    // Epilogue: c = sA*sB*(16384*P1 + 128*P23)
    int rbase = wy * 64 + (lane >> 2);
    int cbase = n0 + wx * 32 + (lane & 3) * 2;
    float sb0[4], sb1[4];
#pragma unroll
    for (int nt = 0; nt < 4; ++nt) {
        sb0[nt] = sB[cbase + nt * 8];
        sb1[nt] = sB[cbase + nt * 8 + 1];
    }
#pragma unroll
    for (int mt = 0; mt < 4; ++mt) {
#pragma unroll
        for (int half = 0; half < 2; ++half) {
            int r = rbase + mt * 16 + half * 8;
            int sl = s_slot[r];
            if (sl < 0) continue;
            float sA = s_asc[r];
            float* orow = (RELU2 ? g_h2 : g_y) + (size_t)sl * NDIM + cbase;
#pragma unroll
            for (int nt = 0; nt < 4; ++nt) {
                float p1a = (float)acc1[mt][nt][half * 2 + 0];
                float p1b = (float)acc1[mt][nt][half * 2 + 1];
                float pa  = (float)acc23[mt][nt][half * 2 + 0];
                float pb  = (float)acc23[mt][nt][half * 2 + 1];
                float v0 = sA * sb0[nt] * fmaf(16384.f, p1a, 128.f * pa);
                float v1 = sA * sb1[nt] * fmaf(16384.f, p1b, 128.f * pb);
                if (RELU2) {
                    v0 = fmaxf(v0, 0.f); v0 *= v0;
                    v1 = fmaxf(v1, 0.f); v1 *= v1;
                }
                *(float2*)(orow + nt * 8) = make_float2(v0, v1);
            }
        }
    }
}

// ---------------------------------------------------------------------------
__global__ void k_combine(float* __restrict__ out, int out_size) {
    int t = blockIdx.x;
    int i = threadIdx.x;
    float w0 = g_w[2 * t];
    float w1 = g_w[2 * t + 1];
    float4 a = ((const float4*)(g_y + (size_t)(2 * t) * DIMSZ))[i];
    float4 b = ((const float4*)(g_y + (size_t)(2 * t + 1) * DIMSZ))[i];
    float4 r;
    r.x = w0 * a.x + w1 * b.x;
    r.y = w0 * a.y + w1 * b.y;
    r.z = w0 * a.z + w1 * b.z;
    r.w = w0 * a.w + w1 * b.w;
    ((float4*)(out + (size_t)t * DIMSZ))[i] = r;
    if (t == 0 && i == 0) {
        for (int j = TOK * DIMSZ; j < out_size; ++j) out[j] = 0.f;  // aux_loss tail
    }
}

// ---------------------------------------------------------------------------
extern "C" void kernel_launch(void* const* d_in, const int* in_sizes, int n_in,
                              void* d_out, int out_size) {
    const float* x   = (const float*)d_in[0];   // [1, 2048, 1024]
    const float* Wr  = (const float*)d_in[1];   // [8, 1024]
    const float* Wfc = (const float*)d_in[2];   // [8, 2048, 1024]
    const float* Wp  = (const float*)d_in[3];   // [8, 1024, 2048]
    float* out = (float*)d_out;

    cudaFuncSetAttribute(k_gemm_i8<DIMSZ, HID, true, 1, 1>,
                         cudaFuncAttributeMaxDynamicSharedMemorySize, GSMEM);
    cudaFuncSetAttribute(k_gemm_i8<HID, DIMSZ, false, 0, 2>,
                         cudaFuncAttributeMaxDynamicSharedMemorySize, GSMEM);

    k_zero_counts<<<1, 32>>>();
    k_router<<<TOK / 8, 256>>>(x, Wr);
    // quantize x / Wfc / Wp (per-row 14-bit -> int8 hi/lo + scale)
    { s8 *qh, *ql; float* sc;
      cudaGetSymbolAddress((void**)&qh, g_xqh); cudaGetSymbolAddress((void**)&ql, g_xql);
      cudaGetSymbolAddress((void**)&sc, g_sx);
      k_quant<DIMSZ><<<TOK, 256>>>(x, qh, ql, sc); }
    { s8 *qh, *ql; float* sc;
      cudaGetSymbolAddress((void**)&qh, g_wfcqh); cudaGetSymbolAddress((void**)&ql, g_wfcql);
      cudaGetSymbolAddress((void**)&sc, g_swfc);
      k_quant<DIMSZ><<<NE * HID, 256>>>(Wfc, qh, ql, sc); }
    { s8 *qh, *ql; float* sc;
      cudaGetSymbolAddress((void**)&qh, g_wpqh); cudaGetSymbolAddress((void**)&ql, g_wpql);
      cudaGetSymbolAddress((void**)&sc, g_swp);
      k_quant<HID><<<NE * DIMSZ, 256>>>(Wp, qh, ql, sc); }

    // GEMM1: h2[slot, H] = relu(x[tok] @ Wfc[e]^T)^2  (fp32 out)
    k_gemm_i8<DIMSZ, HID, true, 1, 1>
        <<<dim3(HID / 64, TOK / 128, NE), 128, GSMEM>>>();
    // quantize h2
    { s8 *qh, *ql; float *sc, *h2;
      cudaGetSymbolAddress((void**)&qh, g_h2qh); cudaGetSymbolAddress((void**)&ql, g_h2ql);
      cudaGetSymbolAddress((void**)&sc, g_sh2);  cudaGetSymbolAddress((void**)&h2, g_h2);
      k_quant<HID><<<NSLOT, 256>>>(h2, qh, ql, sc); }
    // GEMM2: y[slot, D] = h2[slot] @ Wp[e]^T
    k_gemm_i8<HID, DIMSZ, false, 0, 2>
        <<<dim3(DIMSZ / 64, TOK / 128, NE), 128, GSMEM>>>();
    k_combine<<<TOK, 256>>>(out, out_size);
}

// round 10
// speedup vs baseline: 3.6055x; 3.6055x over previous
#include <cuda_runtime.h>
#include <cuda_fp16.h>
#include <cstdint>

#define TOK   2048
#define DIMSZ 1024
#define HID   2048
#define NE    8
#define NSLOT (2 * TOK)

// Scratch (allocation-free: __device__ globals)
__device__ float g_w[NSLOT];
__device__ int   g_cnt[NE];
__device__ int   g_list[NE * TOK];
__device__ __align__(128) __half g_xh[TOK * DIMSZ];
__device__ __align__(128) __half g_xl[TOK * DIMSZ];
__device__ __align__(128) __half g_wfch[NE * HID * DIMSZ];
__device__ __align__(128) __half g_wph[NE * DIMSZ * HID];
__device__ __align__(128) __half g_h2h[NSLOT * HID];
__device__ __align__(128) __half g_h2l[NSLOT * HID];
__device__ float g_y[(size_t)NSLOT * DIMSZ];

// ---------------------------------------------------------------------------
// Helpers
// ---------------------------------------------------------------------------
__device__ __forceinline__ uint32_t smem_u32(const void* p) {
    uint32_t a;
    asm("{ .reg .u64 t; cvta.to.shared.u64 t, %1; cvt.u32.u64 %0, t; }" : "=r"(a) : "l"(p));
    return a;
}
__device__ __forceinline__ void ldm4(uint32_t* r, uint32_t addr) {
    asm volatile("ldmatrix.sync.aligned.m8n8.x4.shared.b16 {%0,%1,%2,%3}, [%4];"
        : "=r"(r[0]), "=r"(r[1]), "=r"(r[2]), "=r"(r[3]) : "r"(addr));
}
__device__ __forceinline__ void mmaf16(float* c, const uint32_t* a, const uint32_t* b) {
    asm volatile(
        "mma.sync.aligned.m16n8k16.row.col.f32.f16.f16.f32 "
        "{%0,%1,%2,%3}, {%4,%5,%6,%7}, {%8,%9}, {%0,%1,%2,%3};"
        : "+f"(c[0]), "+f"(c[1]), "+f"(c[2]), "+f"(c[3])
        : "r"(a[0]), "r"(a[1]), "r"(a[2]), "r"(a[3]), "r"(b[0]), "r"(b[1]));
}
__device__ __forceinline__ void cp16(uint32_t dst, const void* src) {
    asm volatile("cp.async.cg.shared.global [%0], [%1], 16;" :: "r"(dst), "l"(src) : "memory");
}
__device__ __forceinline__ void cp_commit() {
    asm volatile("cp.async.commit_group;" ::: "memory");
}
template<int N> __device__ __forceinline__ void cp_wait() {
    asm volatile("cp.async.wait_group %0;" :: "n"(N) : "memory");
}
// (row, 16B-chunk c in 0..3) -> swizzled byte offset within one 128x64B mat
__device__ __forceinline__ uint32_t swzoff(uint32_t row, uint32_t c) {
    uint32_t q = (((row & 1u) << 2) | c) ^ ((row >> 1) & 7u);
    return ((row >> 1) << 7) + (q << 4);
}

// ---------------------------------------------------------------------------
__global__ void k_zero_counts() {
    if (threadIdx.x < NE) g_cnt[threadIdx.x] = 0;
}

// Split fp32 -> fp16 hi + fp16 lo (x only)
__global__ void k_split_x(const float4* __restrict__ s, int n4) {
    int i = blockIdx.x * 256 + threadIdx.x;
    if (i >= n4) return;
    float4 v = s[i];
    __half2 h0 = __floats2half2_rn(v.x, v.y);
    __half2 h1 = __floats2half2_rn(v.z, v.w);
    float2 f0 = __half22float2(h0);
    float2 f1 = __half22float2(h1);
    __half2 l0 = __floats2half2_rn(v.x - f0.x, v.y - f0.y);
    __half2 l1 = __floats2half2_rn(v.z - f1.x, v.w - f1.y);
    ((uint2*)g_xh)[i] = make_uint2(*(uint32_t*)&h0, *(uint32_t*)&h1);
    ((uint2*)g_xl)[i] = make_uint2(*(uint32_t*)&l0, *(uint32_t*)&l1);
}

// Convert weights fp32 -> single fp16. SEL: 0=Wfc, 1=Wp
template<int SEL>
__global__ void k_cvt_w(const float4* __restrict__ s, int n4) {
    int i = blockIdx.x * 256 + threadIdx.x;
    if (i >= n4) return;
    float4 v = s[i];
    __half2 h0 = __floats2half2_rn(v.x, v.y);
    __half2 h1 = __floats2half2_rn(v.z, v.w);
    uint2* d = (SEL == 0) ? (uint2*)g_wfch : (uint2*)g_wph;
    d[i] = make_uint2(*(uint32_t*)&h0, *(uint32_t*)&h1);
}

// Router: one warp per token. logits -> softmax -> top2 -> renormalize (+1e-8)
__global__ void k_router(const float* __restrict__ x, const float* __restrict__ Wr) {
    int warp = threadIdx.x >> 5;
    int lane = threadIdx.x & 31;
    int t = blockIdx.x * 8 + warp;

    float acc[NE];
#pragma unroll
    for (int e = 0; e < NE; ++e) acc[e] = 0.f;

    const float* xr = x + (size_t)t * DIMSZ;
    for (int i = lane; i < DIMSZ; i += 32) {
        float xv = xr[i];
#pragma unroll
        for (int e = 0; e < NE; ++e) acc[e] = fmaf(xv, Wr[e * DIMSZ + i], acc[e]);
    }
#pragma unroll
    for (int e = 0; e < NE; ++e) {
#pragma unroll
        for (int o = 16; o > 0; o >>= 1)
            acc[e] += __shfl_xor_sync(0xffffffffu, acc[e], o);
    }
    if (lane == 0) {
        float m = acc[0];
#pragma unroll
        for (int e = 1; e < NE; ++e) m = fmaxf(m, acc[e]);
        float p[NE]; float Z = 0.f;
#pragma unroll
        for (int e = 0; e < NE; ++e) { p[e] = expf(acc[e] - m); Z += p[e]; }
        float invZ = 1.f / Z;
#pragma unroll
        for (int e = 0; e < NE; ++e) p[e] *= invZ;

        int e0 = 0;
#pragma unroll
        for (int e = 1; e < NE; ++e) if (p[e] > p[e0]) e0 = e;
        int e1 = (e0 == 0) ? 1 : 0;
#pragma unroll
        for (int e = 0; e < NE; ++e) { if (e != e0 && p[e] > p[e1]) e1 = e; }

        float s = p[e0] + p[e1] + 1e-8f;
        g_w[2 * t]     = p[e0] / s;
        g_w[2 * t + 1] = p[e1] / s;
        int q0 = atomicAdd(&g_cnt[e0], 1); g_list[e0 * TOK + q0] = 2 * t;
        int q1 = atomicAdd(&g_cnt[e1], 1); g_list[e1 * TOK + q1] = 2 * t + 1;
    }
}

// ---------------------------------------------------------------------------
// Grouped GEMM: mma.sync m16n8k16 fp16, 2-pass activation split:
//   C = Ah·B + Al·B     (A split exact to 2^-22; error = fp16 weight rounding)
// CTA = 128 threads (4 warps 2x2), tile 128x128, warp tile 64x64.
// 3-stage circular cp.async pipeline, ONE __syncthreads per K-slab.
// Smem per stage: mats Ah, Al, B, each 128 rows x 64B (32 fp16), XOR-swizzled.
#define MAT      8192
#define STG      (3 * MAT)            // 24576
#define SLOT_OFF (3 * STG)            // 73728
#define AOFF_OFF (SLOT_OFF + 512)
#define GSMEM    (AOFF_OFF + 512)

template<int KDIM, int NDIM, bool RELU2, int SHIFT, int PHASE>
__global__ void __launch_bounds__(128, 2)
k_gemm_f16() {
    constexpr int NSLAB = KDIM / 32;
    const __half* Ah = (PHASE == 1) ? g_xh : g_h2h;
    const __half* Al = (PHASE == 1) ? g_xl : g_h2l;
    const __half* BA = (PHASE == 1) ? g_wfch : g_wph;

    int e   = blockIdx.z;
    int cnt = g_cnt[e];
    int m0  = blockIdx.y * 128;
    if (m0 >= cnt) return;
    int n0  = blockIdx.x * 128;
    const __half* B = BA + (size_t)e * NDIM * KDIM;

    extern __shared__ char smem[];
    uint32_t sb = smem_u32(smem);
    int* s_slot = (int*)(smem + SLOT_OFF);
    int* s_aoff = (int*)(smem + AOFF_OFF);
    int tid = threadIdx.x, w = tid >> 5, lane = tid & 31;

    {
        int idx = m0 + tid;
        int sl  = g_list[e * TOK + ((idx < cnt) ? idx : m0)];
        s_slot[tid] = (idx < cnt) ? sl : -1;
        s_aoff[tid] = (sl >> SHIFT) * KDIM;
    }
    __syncthreads();

    int lrow = lane & 7, lchunk = lane >> 3;
    int raoff[4];
    size_t boff[4];
#pragma unroll
    for (int j = 0; j < 4; ++j) {
        int row = (4 * j + w) * 8 + lrow;
        raoff[j] = s_aoff[row] + lchunk * 8;
        boff[j]  = (size_t)(n0 + row) * KDIM + lchunk * 8;
    }

    // issue one K-slab (32 fp16 per row): 12 cp.async + 1 commit
    auto issue = [&](int ks, int stage) {
        int k0 = ks * 32;
        uint32_t stg = sb + (uint32_t)stage * STG;
#pragma unroll
        for (int j = 0; j < 4; ++j) {
            uint32_t row = (uint32_t)(4 * j + w) * 8 + lrow;
            uint32_t so = stg + swzoff(row, lchunk);
            cp16(so,           Ah + raoff[j] + k0);
            cp16(so + MAT,     Al + raoff[j] + k0);
            cp16(so + 2 * MAT, B  + boff[j] + k0);
        }
        cp_commit();
    };

    int wy = w >> 1, wx = w & 1;
    // ldmatrix per-lane bases (kk=0); kk=1 via ^0x20
    uint32_t aQ = (((lane & 1u) << 2) | (uint32_t)(lane >> 4)) ^ (((uint32_t)(lane & 15) >> 1) & 7u);
    uint32_t aB0 = sb + (uint32_t)((wy * 64 + (lane & 15)) >> 1) * 128 + aQ * 16;
    // B ldm4: pair p covers n-tiles 2p, 2p+1 (16 rows)
    uint32_t brow = (uint32_t)(wx * 64 + ((lane >> 4) & 1) * 8 + (lane & 7));
    uint32_t bc   = (uint32_t)((lane >> 3) & 1);
    uint32_t bQ   = (((brow & 1u) << 2) | bc) ^ ((brow >> 1) & 7u);
    uint32_t bB0  = sb + 2 * MAT + (brow >> 1) * 128 + bQ * 16;

    float acc[4][8][4];
#pragma unroll
    for (int i = 0; i < 4; ++i)
#pragma unroll
        for (int j = 0; j < 8; ++j)
#pragma unroll
            for (int r = 0; r < 4; ++r) acc[i][j][r] = 0.f;

    issue(0, 0);
    issue(1, 1);
    cp_wait<1>();
    __syncthreads();

#pragma unroll 1
    for (int ks = 0; ks < NSLAB; ++ks) {
        int cur = ks % 3;
        // refill the stage freed at the previous barrier (2 slabs in flight)
        if (ks + 2 < NSLAB) issue(ks + 2, (ks + 2) % 3);
        else                cp_commit();   // empty group keeps wait-count uniform

        uint32_t aS = aB0 + (uint32_t)cur * STG;
        uint32_t bS = bB0 + (uint32_t)cur * STG;
#pragma unroll
        for (int kk = 0; kk < 2; ++kk) {
            uint32_t ah[4][4], al[4][4], bb[4][4];
#pragma unroll
            for (int mt = 0; mt < 4; ++mt) {
                uint32_t ad = (aS + mt * 1024) ^ (kk * 0x20);
                ldm4(ah[mt], ad);
                ldm4(al[mt], ad + MAT);
            }
#pragma unroll
            for (int p = 0; p < 4; ++p) {
                uint32_t bd = (bS + p * 1024) ^ (kk * 0x20);
                ldm4(bb[p], bd);
            }
#pragma unroll
            for (int mt = 0; mt < 4; ++mt)
#pragma unroll
                for (int nt = 0; nt < 8; ++nt) {
                    float* c = acc[mt][nt];
                    const uint32_t* pb = &bb[nt >> 1][(nt & 1) * 2];
                    mmaf16(c, ah[mt], pb);
                    mmaf16(c, al[mt], pb);
                }
        }
        cp_wait<1>();      // slab ks+1 landed
        __syncthreads();   // stage cur free for refill next iteration
    }

    // Epilogue
    int rbase = wy * 64 + (lane >> 2);
    int cbase = n0 + wx * 64 + (lane & 3) * 2;
#pragma unroll
    for (int mt = 0; mt < 4; ++mt) {
#pragma unroll
        for (int half = 0; half < 2; ++half) {
            int sl = s_slot[rbase + mt * 16 + half * 8];
            if (sl < 0) continue;
            if (RELU2) {
                uint32_t* oh = (uint32_t*)(g_h2h + (size_t)sl * NDIM + cbase);
                uint32_t* ol = (uint32_t*)(g_h2l + (size_t)sl * NDIM + cbase);
#pragma unroll
                for (int nt = 0; nt < 8; ++nt) {
                    float v0 = acc[mt][nt][half * 2 + 0];
                    float v1 = acc[mt][nt][half * 2 + 1];
                    v0 = fmaxf(v0, 0.f); v0 *= v0;
                    v1 = fmaxf(v1, 0.f); v1 *= v1;
                    __half2 hp = __floats2half2_rn(v0, v1);
                    float2 hf = __half22float2(hp);
                    __half2 lp = __floats2half2_rn(v0 - hf.x, v1 - hf.y);
                    oh[nt * 4] = *(uint32_t*)&hp;
                    ol[nt * 4] = *(uint32_t*)&lp;
                }
            } else {
                float* oy = g_y + (size_t)sl * NDIM + cbase;
#pragma unroll
                for (int nt = 0; nt < 8; ++nt) {
                    *(float2*)(oy + nt * 8) =
                        make_float2(acc[mt][nt][half * 2 + 0], acc[mt][nt][half * 2 + 1]);
                }
            }
        }
    }
}

// ---------------------------------------------------------------------------
__global__ void k_combine(float* __restrict__ out, int out_size) {
    int t = blockIdx.x;
    int i = threadIdx.x;
    float w0 = g_w[2 * t];
    float w1 = g_w[2 * t + 1];
    float4 a = ((const float4*)(g_y + (size_t)(2 * t) * DIMSZ))[i];
    float4 b = ((const float4*)(g_y + (size_t)(2 * t + 1) * DIMSZ))[i];
    float4 r;
    r.x = w0 * a.x + w1 * b.x;
    r.y = w0 * a.y + w1 * b.y;
    r.z = w0 * a.z + w1 * b.z;
    r.w = w0 * a.w + w1 * b.w;
    ((float4*)(out + (size_t)t * DIMSZ))[i] = r;
    if (t == 0 && i == 0) {
        for (int j = TOK * DIMSZ; j < out_size; ++j) out[j] = 0.f;  // aux_loss tail
    }
}

// ---------------------------------------------------------------------------
extern "C" void kernel_launch(void* const* d_in, const int* in_sizes, int n_in,
                              void* d_out, int out_size) {
    const float* x   = (const float*)d_in[0];   // [1, 2048, 1024]
    const float* Wr  = (const float*)d_in[1];   // [8, 1024]
    const float* Wfc = (const float*)d_in[2];   // [8, 2048, 1024]
    const float* Wp  = (const float*)d_in[3];   // [8, 1024, 2048]
    float* out = (float*)d_out;

    cudaFuncSetAttribute(k_gemm_f16<DIMSZ, HID, true, 1, 1>,
                         cudaFuncAttributeMaxDynamicSharedMemorySize, GSMEM);
    cudaFuncSetAttribute(k_gemm_f16<HID, DIMSZ, false, 0, 2>,
                         cudaFuncAttributeMaxDynamicSharedMemorySize, GSMEM);

    k_zero_counts<<<1, 32>>>();
    k_router<<<TOK / 8, 256>>>(x, Wr);
    k_split_x<<<(TOK * DIMSZ / 4 + 255) / 256, 256>>>((const float4*)x, TOK * DIMSZ / 4);
    k_cvt_w<0><<<(NE * HID * DIMSZ / 4 + 255) / 256, 256>>>((const float4*)Wfc, NE * HID * DIMSZ / 4);
    k_cvt_w<1><<<(NE * DIMSZ * HID / 4 + 255) / 256, 256>>>((const float4*)Wp, NE * DIMSZ * HID / 4);
    // GEMM1: h2[slot, H] = relu(x[tok] @ Wfc[e]^T)^2  (fp16 hi/lo output)
    k_gemm_f16<DIMSZ, HID, true, 1, 1>
        <<<dim3(HID / 128, TOK / 128, NE), 128, GSMEM>>>();
    // GEMM2: y[slot, D] = h2[slot] @ Wp[e]^T
    k_gemm_f16<HID, DIMSZ, false, 0, 2>
        <<<dim3(DIMSZ / 128, TOK / 128, NE), 128, GSMEM>>>();
    k_combine<<<TOK, 256>>>(out, out_size);
}

// round 11
// speedup vs baseline: 4.0011x; 1.1097x over previous
#include <cuda_runtime.h>
#include <cuda_fp16.h>
#include <cstdint>

#define TOK   2048
#define DIMSZ 1024
#define HID   2048
#define NE    8
#define NSLOT (2 * TOK)

// Scratch (allocation-free: __device__ globals)
__device__ float g_w[NSLOT];
__device__ int   g_cnt[NE];
__device__ int   g_list[NE * TOK];
__device__ __align__(128) __half g_xh[TOK * DIMSZ];
__device__ __align__(128) __half g_wfch[NE * HID * DIMSZ];
__device__ __align__(128) __half g_wph[NE * DIMSZ * HID];
__device__ __align__(128) __half g_h2h[NSLOT * HID];
__device__ float g_y[(size_t)NSLOT * DIMSZ];

// ---------------------------------------------------------------------------
// Helpers
// ---------------------------------------------------------------------------
__device__ __forceinline__ uint32_t smem_u32(const void* p) {
    uint32_t a;
    asm("{ .reg .u64 t; cvta.to.shared.u64 t, %1; cvt.u32.u64 %0, t; }" : "=r"(a) : "l"(p));
    return a;
}
__device__ __forceinline__ void ldm4(uint32_t* r, uint32_t addr) {
    asm volatile("ldmatrix.sync.aligned.m8n8.x4.shared.b16 {%0,%1,%2,%3}, [%4];"
        : "=r"(r[0]), "=r"(r[1]), "=r"(r[2]), "=r"(r[3]) : "r"(addr));
}
__device__ __forceinline__ void mmaf16(float* c, const uint32_t* a, const uint32_t* b) {
    asm volatile(
        "mma.sync.aligned.m16n8k16.row.col.f32.f16.f16.f32 "
        "{%0,%1,%2,%3}, {%4,%5,%6,%7}, {%8,%9}, {%0,%1,%2,%3};"
        : "+f"(c[0]), "+f"(c[1]), "+f"(c[2]), "+f"(c[3])
        : "r"(a[0]), "r"(a[1]), "r"(a[2]), "r"(a[3]), "r"(b[0]), "r"(b[1]));
}
__device__ __forceinline__ void cp16(uint32_t dst, const void* src) {
    asm volatile("cp.async.cg.shared.global [%0], [%1], 16;" :: "r"(dst), "l"(src) : "memory");
}
__device__ __forceinline__ void cp_commit() {
    asm volatile("cp.async.commit_group;" ::: "memory");
}
template<int N> __device__ __forceinline__ void cp_wait() {
    asm volatile("cp.async.wait_group %0;" :: "n"(N) : "memory");
}
// (row, 16B-chunk c in 0..3) -> swizzled byte offset within one 128x64B mat
__device__ __forceinline__ uint32_t swzoff(uint32_t row, uint32_t c) {
    uint32_t q = (((row & 1u) << 2) | c) ^ ((row >> 1) & 7u);
    return ((row >> 1) << 7) + (q << 4);
}

// ---------------------------------------------------------------------------
__global__ void k_zero_counts() {
    if (threadIdx.x < NE) g_cnt[threadIdx.x] = 0;
}

// Convert fp32 -> fp16. SEL: 0=x, 1=Wfc, 2=Wp
template<int SEL>
__global__ void k_cvt(const float4* __restrict__ s, int n4) {
    int i = blockIdx.x * 256 + threadIdx.x;
    if (i >= n4) return;
    float4 v = s[i];
    __half2 h0 = __floats2half2_rn(v.x, v.y);
    __half2 h1 = __floats2half2_rn(v.z, v.w);
    uint2* d = (SEL == 0) ? (uint2*)g_xh : (SEL == 1) ? (uint2*)g_wfch : (uint2*)g_wph;
    d[i] = make_uint2(*(uint32_t*)&h0, *(uint32_t*)&h1);
}

// Router: one warp per token. logits -> softmax -> top2 -> renormalize (+1e-8)
__global__ void k_router(const float* __restrict__ x, const float* __restrict__ Wr) {
    int warp = threadIdx.x >> 5;
    int lane = threadIdx.x & 31;
    int t = blockIdx.x * 8 + warp;

    float acc[NE];
#pragma unroll
    for (int e = 0; e < NE; ++e) acc[e] = 0.f;

    const float* xr = x + (size_t)t * DIMSZ;
    for (int i = lane; i < DIMSZ; i += 32) {
        float xv = xr[i];
#pragma unroll
        for (int e = 0; e < NE; ++e) acc[e] = fmaf(xv, Wr[e * DIMSZ + i], acc[e]);
    }
#pragma unroll
    for (int e = 0; e < NE; ++e) {
#pragma unroll
        for (int o = 16; o > 0; o >>= 1)
            acc[e] += __shfl_xor_sync(0xffffffffu, acc[e], o);
    }
    if (lane == 0) {
        float m = acc[0];
#pragma unroll
        for (int e = 1; e < NE; ++e) m = fmaxf(m, acc[e]);
        float p[NE]; float Z = 0.f;
#pragma unroll
        for (int e = 0; e < NE; ++e) { p[e] = expf(acc[e] - m); Z += p[e]; }
        float invZ = 1.f / Z;
#pragma unroll
        for (int e = 0; e < NE; ++e) p[e] *= invZ;

        int e0 = 0;
#pragma unroll
        for (int e = 1; e < NE; ++e) if (p[e] > p[e0]) e0 = e;
        int e1 = (e0 == 0) ? 1 : 0;
#pragma unroll
        for (int e = 0; e < NE; ++e) { if (e != e0 && p[e] > p[e1]) e1 = e; }

        float s = p[e0] + p[e1] + 1e-8f;
        g_w[2 * t]     = p[e0] / s;
        g_w[2 * t + 1] = p[e1] / s;
        int q0 = atomicAdd(&g_cnt[e0], 1); g_list[e0 * TOK + q0] = 2 * t;
        int q1 = atomicAdd(&g_cnt[e1], 1); g_list[e1 * TOK + q1] = 2 * t + 1;
    }
}

// ---------------------------------------------------------------------------
// Grouped GEMM: mma.sync m16n8k16 fp16 single-pass, fp32 accumulate.
// CTA = 128 threads (4 warps 2x2), tile 128x128, warp tile 64x64.
// 3-stage circular cp.async pipeline, ONE __syncthreads per K-slab.
// Smem per stage: mats A, B, each 128 rows x 64B (32 fp16), XOR-swizzled.
#define MAT      8192
#define STG      (2 * MAT)            // 16384
#define SLOT_OFF (3 * STG)            // 49152
#define AOFF_OFF (SLOT_OFF + 512)
#define GSMEM    (AOFF_OFF + 512)

template<int KDIM, int NDIM, bool RELU2, int SHIFT, int PHASE>
__global__ void __launch_bounds__(128, 2)
k_gemm_f16() {
    constexpr int NSLAB = KDIM / 32;
    const __half* Ah = (PHASE == 1) ? g_xh : g_h2h;
    const __half* BA = (PHASE == 1) ? g_wfch : g_wph;

    int e   = blockIdx.z;
    int cnt = g_cnt[e];
    int m0  = blockIdx.y * 128;
    if (m0 >= cnt) return;
    int n0  = blockIdx.x * 128;
    const __half* B = BA + (size_t)e * NDIM * KDIM;

    extern __shared__ char smem[];
    uint32_t sb = smem_u32(smem);
    int* s_slot = (int*)(smem + SLOT_OFF);
    int* s_aoff = (int*)(smem + AOFF_OFF);
    int tid = threadIdx.x, w = tid >> 5, lane = tid & 31;

    {
        int idx = m0 + tid;
        int sl  = g_list[e * TOK + ((idx < cnt) ? idx : m0)];
        s_slot[tid] = (idx < cnt) ? sl : -1;
        s_aoff[tid] = (sl >> SHIFT) * KDIM;
    }
    __syncthreads();

    int lrow = lane & 7, lchunk = lane >> 3;
    int raoff[4];
    size_t boff[4];
#pragma unroll
    for (int j = 0; j < 4; ++j) {
        int row = (4 * j + w) * 8 + lrow;
        raoff[j] = s_aoff[row] + lchunk * 8;
        boff[j]  = (size_t)(n0 + row) * KDIM + lchunk * 8;
    }

    // issue one K-slab (32 fp16 per row): 8 cp.async + 1 commit
    auto issue = [&](int ks, int stage) {
        int k0 = ks * 32;
        uint32_t stg = sb + (uint32_t)stage * STG;
#pragma unroll
        for (int j = 0; j < 4; ++j) {
            uint32_t row = (uint32_t)(4 * j + w) * 8 + lrow;
            uint32_t so = stg + swzoff(row, lchunk);
            cp16(so,       Ah + raoff[j] + k0);
            cp16(so + MAT, B  + boff[j] + k0);
        }
        cp_commit();
    };

    int wy = w >> 1, wx = w & 1;
    // ldmatrix per-lane bases (kk=0); kk=1 via ^0x20
    uint32_t aQ = (((lane & 1u) << 2) | (uint32_t)(lane >> 4)) ^ (((uint32_t)(lane & 15) >> 1) & 7u);
    uint32_t aB0 = sb + (uint32_t)((wy * 64 + (lane & 15)) >> 1) * 128 + aQ * 16;
    // B ldm4: pair p covers n-tiles 2p, 2p+1 (16 rows)
    uint32_t brow = (uint32_t)(wx * 64 + ((lane >> 4) & 1) * 8 + (lane & 7));
    uint32_t bc   = (uint32_t)((lane >> 3) & 1);
    uint32_t bQ   = (((brow & 1u) << 2) | bc) ^ ((brow >> 1) & 7u);
    uint32_t bB0  = sb + MAT + (brow >> 1) * 128 + bQ * 16;

    float acc[4][8][4];
#pragma unroll
    for (int i = 0; i < 4; ++i)
#pragma unroll
        for (int j = 0; j < 8; ++j)
#pragma unroll
            for (int r = 0; r < 4; ++r) acc[i][j][r] = 0.f;

    issue(0, 0);
    issue(1, 1);
    cp_wait<1>();
    __syncthreads();

#pragma unroll 1
    for (int ks = 0; ks < NSLAB; ++ks) {
        int cur = ks % 3;
        // refill the stage freed at the previous barrier (2 slabs in flight)
        if (ks + 2 < NSLAB) issue(ks + 2, (ks + 2) % 3);
        else                cp_commit();   // empty group keeps wait-count uniform

        uint32_t aS = aB0 + (uint32_t)cur * STG;
        uint32_t bS = bB0 + (uint32_t)cur * STG;
#pragma unroll
        for (int kk = 0; kk < 2; ++kk) {
            uint32_t ah[4][4], bb[4][4];
#pragma unroll
            for (int mt = 0; mt < 4; ++mt)
                ldm4(ah[mt], (aS + mt * 1024) ^ (kk * 0x20));
#pragma unroll
            for (int p = 0; p < 4; ++p)
                ldm4(bb[p], (bS + p * 1024) ^ (kk * 0x20));
#pragma unroll
            for (int mt = 0; mt < 4; ++mt)
#pragma unroll
                for (int nt = 0; nt < 8; ++nt)
                    mmaf16(acc[mt][nt], ah[mt], &bb[nt >> 1][(nt & 1) * 2]);
        }
        cp_wait<1>();      // slab ks+1 landed
        __syncthreads();   // stage cur free for refill next iteration
    }

    // Epilogue
    int rbase = wy * 64 + (lane >> 2);
    int cbase = n0 + wx * 64 + (lane & 3) * 2;
#pragma unroll
    for (int mt = 0; mt < 4; ++mt) {
#pragma unroll
        for (int half = 0; half < 2; ++half) {
            int sl = s_slot[rbase + mt * 16 + half * 8];
            if (sl < 0) continue;
            if (RELU2) {
                uint32_t* oh = (uint32_t*)(g_h2h + (size_t)sl * NDIM + cbase);
#pragma unroll
                for (int nt = 0; nt < 8; ++nt) {
                    float v0 = acc[mt][nt][half * 2 + 0];
                    float v1 = acc[mt][nt][half * 2 + 1];
                    v0 = fmaxf(v0, 0.f); v0 *= v0;
                    v1 = fmaxf(v1, 0.f); v1 *= v1;
                    __half2 hp = __floats2half2_rn(v0, v1);
                    oh[nt * 4] = *(uint32_t*)&hp;
                }
            } else {
                float* oy = g_y + (size_t)sl * NDIM + cbase;
#pragma unroll
                for (int nt = 0; nt < 8; ++nt) {
                    *(float2*)(oy + nt * 8) =
                        make_float2(acc[mt][nt][half * 2 + 0], acc[mt][nt][half * 2 + 1]);
                }
            }
        }
    }
}

// ---------------------------------------------------------------------------
__global__ void k_combine(float* __restrict__ out, int out_size) {
    int t = blockIdx.x;
    int i = threadIdx.x;
    float w0 = g_w[2 * t];
    float w1 = g_w[2 * t + 1];
    float4 a = ((const float4*)(g_y + (size_t)(2 * t) * DIMSZ))[i];
    float4 b = ((const float4*)(g_y + (size_t)(2 * t + 1) * DIMSZ))[i];
    float4 r;
    r.x = w0 * a.x + w1 * b.x;
    r.y = w0 * a.y + w1 * b.y;
    r.z = w0 * a.z + w1 * b.z;
    r.w = w0 * a.w + w1 * b.w;
    ((float4*)(out + (size_t)t * DIMSZ))[i] = r;
    if (t == 0 && i == 0) {
        for (int j = TOK * DIMSZ; j < out_size; ++j) out[j] = 0.f;  // aux_loss tail
    }
}

// ---------------------------------------------------------------------------
extern "C" void kernel_launch(void* const* d_in, const int* in_sizes, int n_in,
                              void* d_out, int out_size) {
    const float* x   = (const float*)d_in[0];   // [1, 2048, 1024]
    const float* Wr  = (const float*)d_in[1];   // [8, 1024]
    const float* Wfc = (const float*)d_in[2];   // [8, 2048, 1024]
    const float* Wp  = (const float*)d_in[3];   // [8, 1024, 2048]
    float* out = (float*)d_out;

    cudaFuncSetAttribute(k_gemm_f16<DIMSZ, HID, true, 1, 1>,
                         cudaFuncAttributeMaxDynamicSharedMemorySize, GSMEM);
    cudaFuncSetAttribute(k_gemm_f16<HID, DIMSZ, false, 0, 2>,
                         cudaFuncAttributeMaxDynamicSharedMemorySize, GSMEM);

    k_zero_counts<<<1, 32>>>();
    k_router<<<TOK / 8, 256>>>(x, Wr);
    k_cvt<0><<<(TOK * DIMSZ / 4 + 255) / 256, 256>>>((const float4*)x, TOK * DIMSZ / 4);
    k_cvt<1><<<(NE * HID * DIMSZ / 4 + 255) / 256, 256>>>((const float4*)Wfc, NE * HID * DIMSZ / 4);
    k_cvt<2><<<(NE * DIMSZ * HID / 4 + 255) / 256, 256>>>((const float4*)Wp, NE * DIMSZ * HID / 4);
    // GEMM1: h2[slot, H] = relu(x[tok] @ Wfc[e]^T)^2  (fp16 output)
    k_gemm_f16<DIMSZ, HID, true, 1, 1>
        <<<dim3(HID / 128, TOK / 128, NE), 128, GSMEM>>>();
    // GEMM2: y[slot, D] = h2[slot] @ Wp[e]^T
    k_gemm_f16<HID, DIMSZ, false, 0, 2>
        <<<dim3(DIMSZ / 128, TOK / 128, NE), 128, GSMEM>>>();
    k_combine<<<TOK, 256>>>(out, out_size);
}